// round 2
// baseline (speedup 1.0000x reference)
#include <cuda_runtime.h>
#include <math.h>

// Problem constants
#define B_    512
#define U_    256
#define T_    256
#define NCW   2048   // 8*U

// Tiling
#define BM      64    // batch rows per block
#define BUU     16    // units per block -> 128 GEMM columns (8 gates x 16 units)
#define NCOL    128
#define KT      32    // K-tile
#define NTHREADS 256

// Padded smem leading dims (bank-conflict avoidance)
#define HS_LD   36
#define WS_LD   132
#define MS_LD   132

// Ping-pong state buffers (d_out serves as parity-0 h buffer)
__device__ float g_h1[B_ * U_];
__device__ float g_c0[B_ * U_];
__device__ float g_c1[B_ * U_];

__global__ void init_zero_kernel(float* __restrict__ h0) {
    int i = blockIdx.x * blockDim.x + threadIdx.x;
    if (i < B_ * U_) {
        h0[i]   = 0.0f;
        g_c0[i] = 0.0f;
    }
}

__device__ __forceinline__ float sigf(float v) {
    return 1.0f / (1.0f + __expf(-v));
}

struct SmemT {
    union {
        struct {
            float hs[BM][HS_LD];   // h tile, row-major [row][k]
            float ws[KT][WS_LD];   // W tile, [k][c], c = g*16 + uu
        } a;
        float ms[BM][MS_LD];       // staged m tile for epilogue
    } u;
    float ksh[NCOL];               // kernel slice, index c = g*16+uu
    float xs[BM];                  // x[:, t] slice
};

__global__ __launch_bounds__(NTHREADS, 1)
void nas_step_kernel(float* __restrict__ h_ext,     // parity-0 h buffer (= d_out)
                     const float* __restrict__ W,
                     const float* __restrict__ kern,
                     const float* __restrict__ x,
                     int t)
{
    __shared__ SmemT s;

    const float* h_in  = (t & 1) ? g_h1  : h_ext;
    float*       h_out = (t & 1) ? h_ext : g_h1;
    const float* c_in  = (t & 1) ? g_c1  : g_c0;
    float*       c_out = (t & 1) ? g_c0  : g_c1;

    const int tid = threadIdx.x;
    const int b0  = blockIdx.x * BM;
    const int u0  = blockIdx.y * BUU;

    if (tid < NCOL) {
        int g  = tid >> 4;
        int uu = tid & 15;
        s.ksh[tid] = kern[g * U_ + u0 + uu];
    }
    if (tid < BM) {
        s.xs[tid] = x[(b0 + tid) * U_ + t];
    }

    const int col_t = tid & 15;   // 16 column-groups, each 8 cols
    const int row_t = tid >> 4;   // 16 row-groups, each 4 rows

    float acc[4][8];
    #pragma unroll
    for (int i = 0; i < 4; i++)
        #pragma unroll
        for (int j = 0; j < 8; j++)
            acc[i][j] = 0.0f;

    for (int kt = 0; kt < U_ / KT; kt++) {
        const int k0 = kt * KT;

        // Load h tile: 64 rows x 32 k = 512 float4, 2 per thread (coalesced)
        #pragma unroll
        for (int it = 0; it < 2; it++) {
            int f4  = it * NTHREADS + tid;
            int row = f4 >> 3;          // 8 float4 per row
            int kq  = f4 & 7;
            const float4 v = *reinterpret_cast<const float4*>(
                &h_in[(b0 + row) * U_ + k0 + kq * 4]);
            *reinterpret_cast<float4*>(&s.u.a.hs[row][kq * 4]) = v;
        }
        // Load W tile: 32 k x 128 cols = 1024 float4, 4 per thread.
        // Column c = g*16 + uu maps to global column g*256 + u0 + uu.
        #pragma unroll
        for (int it = 0; it < 4; it++) {
            int f4 = it * NTHREADS + tid;
            int k  = f4 >> 5;           // 32 float4 per k-row
            int cg = f4 & 31;
            int g  = cg >> 2;
            int q  = cg & 3;
            const float4 v = *reinterpret_cast<const float4*>(
                &W[(size_t)(k0 + k) * NCW + g * U_ + u0 + q * 4]);
            *reinterpret_cast<float4*>(&s.u.a.ws[k][cg * 4]) = v;
        }
        __syncthreads();

        #pragma unroll
        for (int k = 0; k < KT; k++) {
            float4 bv0 = *reinterpret_cast<const float4*>(&s.u.a.ws[k][col_t * 8]);
            float4 bv1 = *reinterpret_cast<const float4*>(&s.u.a.ws[k][col_t * 8 + 4]);
            float av[4];
            #pragma unroll
            for (int i = 0; i < 4; i++)
                av[i] = s.u.a.hs[row_t * 4 + i][k];
            #pragma unroll
            for (int i = 0; i < 4; i++) {
                acc[i][0] += av[i] * bv0.x;
                acc[i][1] += av[i] * bv0.y;
                acc[i][2] += av[i] * bv0.z;
                acc[i][3] += av[i] * bv0.w;
                acc[i][4] += av[i] * bv1.x;
                acc[i][5] += av[i] * bv1.y;
                acc[i][6] += av[i] * bv1.z;
                acc[i][7] += av[i] * bv1.w;
            }
        }
        __syncthreads();
    }

    // Stage m tile into smem so each thread can gather all 8 gates of a unit.
    #pragma unroll
    for (int i = 0; i < 4; i++) {
        int row = row_t * 4 + i;
        *reinterpret_cast<float4*>(&s.u.ms[row][col_t * 8]) =
            make_float4(acc[i][0], acc[i][1], acc[i][2], acc[i][3]);
        *reinterpret_cast<float4*>(&s.u.ms[row][col_t * 8 + 4]) =
            make_float4(acc[i][4], acc[i][5], acc[i][6], acc[i][7]);
    }
    __syncthreads();

    // Elementwise NASCell wiring: 64x16 = 1024 elements, 4 per thread.
    #pragma unroll
    for (int it = 0; it < 4; it++) {
        int e   = it * NTHREADS + tid;
        int uu  = e & 15;
        int row = e >> 4;
        float xv  = s.xs[row];
        int gidx  = (b0 + row) * U_ + u0 + uu;
        float cin = c_in[gidx];

        float m[8], iv[8];
        #pragma unroll
        for (int g = 0; g < 8; g++) {
            m[g]  = s.u.ms[row][g * 16 + uu];
            iv[g] = xv * s.ksh[g * 16 + uu];
        }

        float l10 = sigf(iv[0] + m[0]);
        float l11 = fmaxf(iv[1] + m[1], 0.0f);
        float l12 = sigf(iv[2] + m[2]);
        float l13 = fmaxf(iv[3] * m[3], 0.0f);
        float l14 = tanhf(iv[4] + m[4]);
        float l15 = sigf(iv[5] + m[5]);
        float l16 = tanhf(iv[6] + m[6]);
        float l17 = sigf(iv[7] + m[7]);

        float l20 = tanhf(l10 * l11);
        float l21 = tanhf(l12 + l13);
        float l22 = tanhf(l14 * l15);
        float l23 = sigf(l16 + l17);

        l20 = tanhf(l20 + cin);
        float nc  = l20 * l21;
        float l31 = tanhf(l22 + l23);
        float nh  = tanhf(nc * l31);

        c_out[gidx] = nc;
        h_out[gidx] = nh;
    }
}

extern "C" void kernel_launch(void* const* d_in, const int* in_sizes, int n_in,
                              void* d_out, int out_size) {
    const float* x    = nullptr;
    const float* kern = nullptr;
    const float* W    = nullptr;
    for (int i = 0; i < n_in; i++) {
        if (in_sizes[i] == B_ * U_)       x    = (const float*)d_in[i];
        else if (in_sizes[i] == 8 * U_)   kern = (const float*)d_in[i];
        else if (in_sizes[i] == U_ * NCW) W    = (const float*)d_in[i];
    }
    float* h0 = (float*)d_out;   // parity-0 h buffer; final h lands here (T even)

    init_zero_kernel<<<(B_ * U_ + 255) / 256, 256>>>(h0);

    dim3 grid(B_ / BM, U_ / BUU);  // 8 x 16 = 128 blocks
    for (int t = 0; t < T_; t++) {
        nas_step_kernel<<<grid, NTHREADS>>>(h0, W, kern, x, t);
    }
}

// round 3
// speedup vs baseline: 1.1922x; 1.1922x over previous
#include <cuda_runtime.h>
#include <math.h>

// Problem constants
#define B_    512
#define U_    256
#define T_    256
#define NCW   2048   // 8*U

// Decomposition: 8 batch-blocks x 16 unit-blocks = 128 persistent CTAs
#define NBLK     128
#define NTHREADS 256
#define BM       64     // batch rows per block
#define BUU      16     // units per block
#define NCOL     128    // 8 gates * 16 units

// Padded smem leading dims
#define WS_LD 132       // W tile  [256][132]
#define HS_LD 260       // h tile  [64][260]
#define MS_LD 144       // m stage [64][144]  (144%32==16 -> conflict-free epilogue reads)

#define WS_FLOATS (U_ * WS_LD)    // 33792
#define HS_FLOATS (BM * HS_LD)    // 16640
#define SMEM_BYTES ((WS_FLOATS + HS_FLOATS) * 4)   // 201728 bytes

// h ping-pong buffers (c never leaves registers)
__device__ float g_hA[B_ * U_];
__device__ float g_hB[B_ * U_];
// monotonic grid-barrier counter (never reset; wrap-safe; replay-safe)
__device__ unsigned g_arrive;

// ---- packed f32x2 helpers -------------------------------------------------
__device__ __forceinline__ unsigned long long pack2(float a) {
    unsigned long long r;
    asm("mov.b64 %0, {%1, %1};" : "=l"(r) : "f"(a));
    return r;
}
__device__ __forceinline__ void fma2(unsigned long long& d,
                                     unsigned long long a,
                                     unsigned long long b) {
    asm("fma.rn.f32x2 %0, %1, %2, %0;" : "+l"(d) : "l"(a), "l"(b));
}
__device__ __forceinline__ float2 unpack2(unsigned long long v) {
    float2 f;
    asm("mov.b64 {%0, %1}, %2;" : "=f"(f.x), "=f"(f.y) : "l"(v));
    return f;
}

// ---- fast activations (MUFU.EX2-based, rel err ~1e-6) ---------------------
__device__ __forceinline__ float sigf(float v) {
    return __fdividef(1.0f, 1.0f + __expf(-v));
}
__device__ __forceinline__ float tanhf_fast(float v) {
    // tanh(x) = 2*sigmoid(2x) - 1 ; robust for all finite x
    return fmaf(2.0f, sigf(2.0f * v), -1.0f);
}

// ---- grid barrier ---------------------------------------------------------
__device__ __forceinline__ void grid_barrier(int tid) {
    __syncthreads();
    if (tid == 0) {
        __threadfence();                       // publish h stores
        unsigned ticket = atomicAdd(&g_arrive, 1u);
        unsigned target = ticket - (ticket % NBLK) + NBLK;
        while ((int)(atomicAdd(&g_arrive, 0u) - target) < 0) {
            __nanosleep(64);
        }
        __threadfence();
    }
    __syncthreads();
}

extern __shared__ float smem[];

__global__ __launch_bounds__(NTHREADS, 1)
void nas_persistent(float* __restrict__ out,
                    const float* __restrict__ W,
                    const float* __restrict__ kern,
                    const float* __restrict__ x)
{
    float* ws = smem;                 // [U_][WS_LD]
    float* hs = smem + WS_FLOATS;     // [BM][HS_LD]; aliased by ms [BM][MS_LD]
    __shared__ float ksh[NCOL];
    __shared__ float xs[BM];

    const int tid = threadIdx.x;
    const int bx  = blockIdx.x & 7;    // batch block
    const int by  = blockIdx.x >> 3;   // unit block
    const int b0  = bx * BM;
    const int u0  = by * BUU;

    // ---- Prologue: W slice (256 x 128 cols) -> smem, once for all steps ----
    #pragma unroll
    for (int it = 0; it < 32; it++) {
        int f4 = it * NTHREADS + tid;  // 8192 float4 total
        int k  = f4 >> 5;
        int cg = f4 & 31;
        int g  = cg >> 2;
        int q  = cg & 3;
        const float4 v = *reinterpret_cast<const float4*>(
            &W[(size_t)k * NCW + g * U_ + u0 + q * 4]);
        *reinterpret_cast<float4*>(&ws[k * WS_LD + cg * 4]) = v;
    }
    if (tid < NCOL) {
        ksh[tid] = kern[(tid >> 4) * U_ + u0 + (tid & 15)];
    }

    float creg[4] = {0.0f, 0.0f, 0.0f, 0.0f};   // cell state, register-resident

    const int col_t = tid & 15;   // 16 col-groups of 8 GEMM columns
    const int row_t = tid >> 4;   // 16 row-groups of 4 batch rows

    for (int t = 0; t < T_; t++) {
        const float* hin  = (t & 1) ? g_hB : g_hA;
        float*       hout = (t == T_ - 1) ? out : ((t & 1) ? g_hA : g_hB);

        if (tid < BM) xs[tid] = x[(b0 + tid) * U_ + t];

        unsigned long long acc[4][4];
        #pragma unroll
        for (int i = 0; i < 4; i++)
            #pragma unroll
            for (int j = 0; j < 4; j++)
                acc[i][j] = 0ULL;

        if (t > 0) {
            // Load h tile (64 x 256) with L1 bypass (cross-SM producer)
            #pragma unroll
            for (int it = 0; it < 16; it++) {
                int f4  = it * NTHREADS + tid;   // 4096 float4
                int row = f4 >> 6;
                int q   = f4 & 63;
                const float4 v = __ldcg(reinterpret_cast<const float4*>(
                    &hin[(b0 + row) * U_ + q * 4]));
                *reinterpret_cast<float4*>(&hs[row * HS_LD + q * 4]) = v;
            }
            __syncthreads();

            // GEMM: m[64x128] += h[64x256] @ Wsmem[256x128], packed f32x2
            #pragma unroll 8
            for (int k = 0; k < U_; k++) {
                unsigned long long b2[4];
                #pragma unroll
                for (int j = 0; j < 4; j++)
                    b2[j] = *reinterpret_cast<const unsigned long long*>(
                        &ws[k * WS_LD + col_t * 8 + j * 2]);
                #pragma unroll
                for (int i = 0; i < 4; i++) {
                    unsigned long long a2 = pack2(hs[(row_t * 4 + i) * HS_LD + k]);
                    #pragma unroll
                    for (int j = 0; j < 4; j++)
                        fma2(acc[i][j], a2, b2[j]);
                }
            }
            __syncthreads();   // all warps done reading hs before it becomes ms
        }

        // ---- Stage m tile (aliases hs) so each thread gathers its 8 gates --
        float* ms = hs;
        #pragma unroll
        for (int i = 0; i < 4; i++) {
            int row = row_t * 4 + i;
            #pragma unroll
            for (int j = 0; j < 4; j++)
                *reinterpret_cast<unsigned long long*>(
                    &ms[row * MS_LD + col_t * 8 + j * 2]) = acc[i][j];
        }
        __syncthreads();

        // ---- NASCell epilogue: 1024 elements, 4 per thread ----------------
        #pragma unroll
        for (int it = 0; it < 4; it++) {
            int e   = it * NTHREADS + tid;
            int uu  = e & 15;
            int row = e >> 4;
            float xv = xs[row];

            float m[8], iv[8];
            #pragma unroll
            for (int g = 0; g < 8; g++) {
                m[g]  = ms[row * MS_LD + g * 16 + uu];
                iv[g] = xv * ksh[g * 16 + uu];
            }

            float l10 = sigf(iv[0] + m[0]);
            float l11 = fmaxf(iv[1] + m[1], 0.0f);
            float l12 = sigf(iv[2] + m[2]);
            float l13 = fmaxf(iv[3] * m[3], 0.0f);
            float l14 = tanhf_fast(iv[4] + m[4]);
            float l15 = sigf(iv[5] + m[5]);
            float l16 = tanhf_fast(iv[6] + m[6]);
            float l17 = sigf(iv[7] + m[7]);

            float l20 = tanhf_fast(l10 * l11);
            float l21 = tanhf_fast(l12 + l13);
            float l22 = tanhf_fast(l14 * l15);
            float l23 = sigf(l16 + l17);

            l20 = tanhf_fast(l20 + creg[it]);
            float nc  = l20 * l21;
            float l31 = tanhf_fast(l22 + l23);
            float nh  = tanhf_fast(nc * l31);

            creg[it] = nc;
            hout[(b0 + row) * U_ + u0 + uu] = nh;
        }

        if (t != T_ - 1) grid_barrier(tid);
    }
}

extern "C" void kernel_launch(void* const* d_in, const int* in_sizes, int n_in,
                              void* d_out, int out_size) {
    const float* x    = nullptr;
    const float* kern = nullptr;
    const float* W    = nullptr;
    for (int i = 0; i < n_in; i++) {
        if (in_sizes[i] == B_ * U_)       x    = (const float*)d_in[i];
        else if (in_sizes[i] == 8 * U_)   kern = (const float*)d_in[i];
        else if (in_sizes[i] == U_ * NCW) W    = (const float*)d_in[i];
    }
    float* out = (float*)d_out;

    cudaFuncSetAttribute(nas_persistent,
                         cudaFuncAttributeMaxDynamicSharedMemorySize, SMEM_BYTES);
    nas_persistent<<<NBLK, NTHREADS, SMEM_BYTES>>>(out, W, kern, x);
}

// round 4
// speedup vs baseline: 1.1981x; 1.0049x over previous
#include <cuda_runtime.h>
#include <math.h>

// Problem constants
#define B_    512
#define U_    256
#define T_    256
#define NCW   2048   // 8*U

// Decomposition: 8 batch-blocks x 16 unit-blocks = 128 persistent CTAs
#define NBLK     128
#define NTHREADS 256
#define BM       64     // batch rows per block
#define BUU      16     // units per block
#define NCOL     128    // 8 gates * 16 units

// Padded smem leading dims
#define WS_LD 132       // W tile  [256][132]   (528 B/row, 16B aligned)
#define HS_LD 260       // h tile  [64][260]    (1040 B/row, 16B aligned)
#define MS_LD 144       // m stage [64][144]

#define WS_FLOATS (U_ * WS_LD)    // 33792
#define HS_FLOATS (BM * HS_LD)    // 16640
#define SMEM_BYTES ((WS_FLOATS + HS_FLOATS) * 4)   // 201728 bytes

// h ping-pong buffers (c never leaves registers)
__device__ float g_hA[B_ * U_];
__device__ float g_hB[B_ * U_];
// monotonic grid-barrier counter (never reset; wrap-safe; replay-safe)
__device__ unsigned g_arrive;

// ---- packed f32x2 helpers -------------------------------------------------
__device__ __forceinline__ unsigned long long pack2(float a) {
    unsigned long long r;
    asm("mov.b64 %0, {%1, %1};" : "=l"(r) : "f"(a));
    return r;
}
__device__ __forceinline__ void fma2(unsigned long long& d,
                                     unsigned long long a,
                                     unsigned long long b) {
    asm("fma.rn.f32x2 %0, %1, %2, %0;" : "+l"(d) : "l"(a), "l"(b));
}

// ---- fast activations (MUFU.EX2-based) ------------------------------------
__device__ __forceinline__ float sigf(float v) {
    return __fdividef(1.0f, 1.0f + __expf(-v));
}
__device__ __forceinline__ float tanhf_fast(float v) {
    return fmaf(2.0f, sigf(2.0f * v), -1.0f);
}

// ---- grid barrier (monotonic ticket; volatile-poll) ------------------------
__device__ __forceinline__ void grid_barrier(int tid) {
    __syncthreads();
    if (tid == 0) {
        __threadfence();                       // publish h stores
        unsigned ticket = atomicAdd(&g_arrive, 1u);
        unsigned target = ticket - (ticket % NBLK) + NBLK;
        volatile unsigned* p = &g_arrive;
        while ((int)(*p - target) < 0) {
            __nanosleep(32);
        }
        __threadfence();
    }
    __syncthreads();
}

extern __shared__ float smem[];

__global__ __launch_bounds__(NTHREADS, 1)
void nas_persistent(float* __restrict__ out,
                    const float* __restrict__ W,
                    const float* __restrict__ kern,
                    const float* __restrict__ x)
{
    float* ws = smem;                 // [U_][WS_LD]
    float* hs = smem + WS_FLOATS;     // [BM][HS_LD]; aliased by ms [BM][MS_LD]
    __shared__ float ksh[NCOL];
    __shared__ float xs[BM];

    const int tid = threadIdx.x;
    const int bx  = blockIdx.x & 7;    // batch block
    const int by  = blockIdx.x >> 3;   // unit block
    const int b0  = bx * BM;
    const int u0  = by * BUU;

    // ---- Prologue: W slice (256 x 128 cols) -> smem, once for all steps ----
    #pragma unroll
    for (int it = 0; it < 32; it++) {
        int f4 = it * NTHREADS + tid;  // 8192 float4 total
        int k  = f4 >> 5;
        int cg = f4 & 31;
        int g  = cg >> 2;
        int q  = cg & 3;
        const float4 v = *reinterpret_cast<const float4*>(
            &W[(size_t)k * NCW + g * U_ + u0 + q * 4]);
        *reinterpret_cast<float4*>(&ws[k * WS_LD + cg * 4]) = v;
    }
    if (tid < NCOL) {
        ksh[tid] = kern[(tid >> 4) * U_ + u0 + (tid & 15)];
    }

    float creg[4] = {0.0f, 0.0f, 0.0f, 0.0f};   // cell state, register-resident

    const int col_t = tid & 15;   // 16 col-groups of 8 GEMM columns
    const int row_t = tid >> 4;   // 16 row-groups of 4 batch rows

    for (int t = 0; t < T_; t++) {
        const float* hin  = (t & 1) ? g_hB : g_hA;
        float*       hout = (t == T_ - 1) ? out : ((t & 1) ? g_hA : g_hB);

        if (tid < BM) xs[tid] = x[(b0 + tid) * U_ + t];

        unsigned long long acc[4][4];
        #pragma unroll
        for (int i = 0; i < 4; i++)
            #pragma unroll
            for (int j = 0; j < 4; j++)
                acc[i][j] = 0ULL;

        if (t > 0) {
            // Load h tile (64 x 256) with L1 bypass (cross-SM producer)
            #pragma unroll
            for (int it = 0; it < 16; it++) {
                int f4  = it * NTHREADS + tid;   // 4096 float4
                int row = f4 >> 6;
                int q   = f4 & 63;
                const float4 v = __ldcg(reinterpret_cast<const float4*>(
                    &hin[(b0 + row) * U_ + q * 4]));
                *reinterpret_cast<float4*>(&hs[row * HS_LD + q * 4]) = v;
            }
            __syncthreads();

            // GEMM: m[64x128] += h[64x256] @ Wsmem[256x128], packed f32x2.
            // k processed in chunks of 4: a loaded as one LDS.128 per row per
            // chunk; b as 2x LDS.128 per k. 12 LDS / 64 FMA2 per chunk.
            #pragma unroll 2
            for (int kk = 0; kk < U_; kk += 4) {
                float4 a4[4];
                #pragma unroll
                for (int i = 0; i < 4; i++)
                    a4[i] = *reinterpret_cast<const float4*>(
                        &hs[(row_t * 4 + i) * HS_LD + kk]);
                #pragma unroll
                for (int dk = 0; dk < 4; dk++) {
                    const float* wrow = &ws[(kk + dk) * WS_LD + col_t * 8];
                    ulonglong2 b01 = *reinterpret_cast<const ulonglong2*>(wrow);
                    ulonglong2 b23 = *reinterpret_cast<const ulonglong2*>(wrow + 4);
                    #pragma unroll
                    for (int i = 0; i < 4; i++) {
                        float av = (dk == 0) ? a4[i].x :
                                   (dk == 1) ? a4[i].y :
                                   (dk == 2) ? a4[i].z : a4[i].w;
                        unsigned long long a2 = pack2(av);
                        fma2(acc[i][0], a2, b01.x);
                        fma2(acc[i][1], a2, b01.y);
                        fma2(acc[i][2], a2, b23.x);
                        fma2(acc[i][3], a2, b23.y);
                    }
                }
            }
            __syncthreads();   // all warps done reading hs before it becomes ms
        }

        // ---- Stage m tile (aliases hs) so each thread gathers its 8 gates --
        float* ms = hs;
        #pragma unroll
        for (int i = 0; i < 4; i++) {
            int row = row_t * 4 + i;
            #pragma unroll
            for (int j = 0; j < 4; j++)
                *reinterpret_cast<unsigned long long*>(
                    &ms[row * MS_LD + col_t * 8 + j * 2]) = acc[i][j];
        }
        __syncthreads();

        // ---- NASCell epilogue: 1024 elements, 4 per thread ----------------
        #pragma unroll
        for (int it = 0; it < 4; it++) {
            int e   = it * NTHREADS + tid;
            int uu  = e & 15;
            int row = e >> 4;
            float xv = xs[row];

            float m[8], iv[8];
            #pragma unroll
            for (int g = 0; g < 8; g++) {
                m[g]  = ms[row * MS_LD + g * 16 + uu];
                iv[g] = xv * ksh[g * 16 + uu];
            }

            float l10 = sigf(iv[0] + m[0]);
            float l11 = fmaxf(iv[1] + m[1], 0.0f);
            float l12 = sigf(iv[2] + m[2]);
            float l13 = fmaxf(iv[3] * m[3], 0.0f);
            float l14 = tanhf_fast(iv[4] + m[4]);
            float l15 = sigf(iv[5] + m[5]);
            float l16 = tanhf_fast(iv[6] + m[6]);
            float l17 = sigf(iv[7] + m[7]);

            float l20 = tanhf_fast(l10 * l11);
            float l21 = tanhf_fast(l12 + l13);
            float l22 = tanhf_fast(l14 * l15);
            float l23 = sigf(l16 + l17);

            l20 = tanhf_fast(l20 + creg[it]);
            float nc  = l20 * l21;
            float l31 = tanhf_fast(l22 + l23);
            float nh  = tanhf_fast(nc * l31);

            creg[it] = nc;
            hout[(b0 + row) * U_ + u0 + uu] = nh;
        }

        if (t != T_ - 1) grid_barrier(tid);
    }
}

extern "C" void kernel_launch(void* const* d_in, const int* in_sizes, int n_in,
                              void* d_out, int out_size) {
    const float* x    = nullptr;
    const float* kern = nullptr;
    const float* W    = nullptr;
    for (int i = 0; i < n_in; i++) {
        if (in_sizes[i] == B_ * U_)       x    = (const float*)d_in[i];
        else if (in_sizes[i] == 8 * U_)   kern = (const float*)d_in[i];
        else if (in_sizes[i] == U_ * NCW) W    = (const float*)d_in[i];
    }
    float* out = (float*)d_out;

    cudaFuncSetAttribute(nas_persistent,
                         cudaFuncAttributeMaxDynamicSharedMemorySize, SMEM_BYTES);
    nas_persistent<<<NBLK, NTHREADS, SMEM_BYTES>>>(out, W, kern, x);
}